// round 16
// baseline (speedup 1.0000x reference)
#include <cuda_runtime.h>
#include <cuda_fp16.h>
#include <cstdint>

#define NN 100000
#define NE 1600000

#define GRID_WAIT() asm volatile("griddepcontrol.wait;" ::: "memory")

// ---------------- scratch ----------------
__device__ __half g_h [NN * 128];
__device__ __half g_hl[NN * 128];
__device__ __half g_hr[NN * 128];
__device__ float  g_aggx[2 * NN];
__device__ __half g_w2[128 * 256];
__device__ __half g_w3[128 * 64];
__device__ __half g_w4[32 * 64];
__device__ __half g_w5[32 * 64];
__device__ int    g_cnt[NN];        // zero-init at load; k_scan_lb re-zeroes after use
__device__ int    g_rowptr[NN + 1];
__device__ int    g_cursor[NN];
__device__ int    g_csrc[NE];
__device__ unsigned g_state[128];

// ---------------- mma / async helpers ----------------
__device__ __forceinline__ uint32_t smem_u32(const void* p) {
    return (uint32_t)__cvta_generic_to_shared(p);
}
__device__ __forceinline__ void cp16(uint32_t dst, const void* src) {
    asm volatile("cp.async.cg.shared.global [%0], [%1], 16;" :: "r"(dst), "l"(src));
}
__device__ __forceinline__ void cp_commit_wait() {
    asm volatile("cp.async.commit_group;\ncp.async.wait_group 0;" ::: "memory");
}
__device__ __forceinline__ void ldsm_x4(uint32_t& r0, uint32_t& r1, uint32_t& r2, uint32_t& r3, uint32_t a) {
    asm volatile("ldmatrix.sync.aligned.m8n8.x4.shared.b16 {%0,%1,%2,%3},[%4];"
                 : "=r"(r0), "=r"(r1), "=r"(r2), "=r"(r3) : "r"(a));
}
__device__ __forceinline__ void ldsm_x4t(uint32_t& r0, uint32_t& r1, uint32_t& r2, uint32_t& r3, uint32_t a) {
    asm volatile("ldmatrix.sync.aligned.m8n8.x4.trans.shared.b16 {%0,%1,%2,%3},[%4];"
                 : "=r"(r0), "=r"(r1), "=r"(r2), "=r"(r3) : "r"(a));
}
__device__ __forceinline__ void mma16816(float* c, uint32_t a0, uint32_t a1, uint32_t a2, uint32_t a3,
                                         uint32_t b0, uint32_t b1) {
    asm volatile("mma.sync.aligned.m16n8k16.row.col.f32.f16.f16.f32 "
                 "{%0,%1,%2,%3},{%4,%5,%6,%7},{%8,%9},{%0,%1,%2,%3};"
                 : "+f"(c[0]), "+f"(c[1]), "+f"(c[2]), "+f"(c[3])
                 : "r"(a0), "r"(a1), "r"(a2), "r"(a3), "r"(b0), "r"(b1));
}

// ---------------- count (vectorized) + weight pack + zero state/aggx ----------------
__global__ void k_count(const int* __restrict__ ei, int* __restrict__ cnt, int E,
                        const float* Wl2, const float* Wr2, const float* Wl3, const float* Wr3,
                        const float* Wl4, const float* Wr4, const float* Wl5, const float* Wr5,
                        __half* w2, __half* w3, __half* w4, __half* w5,
                        unsigned* state, float* aggx, int n) {
    int q = blockIdx.x * blockDim.x + threadIdx.x;
    int e = q * 4;
    if (e + 3 < E) {
        uint4 d4 = *(const uint4*)&ei[E + e];
        atomicAdd(&cnt[d4.x], 1);
        atomicAdd(&cnt[d4.y], 1);
        atomicAdd(&cnt[d4.z], 1);
        atomicAdd(&cnt[d4.w], 1);
    } else {
        for (int t = e; t < E; t++) atomicAdd(&cnt[ei[E + t]], 1);
    }
    if (blockIdx.x == 0 && threadIdx.x < 128) state[threadIdx.x] = 0u;
    if (q < (2 * n + 3) / 4) *(float4*)&aggx[q * 4] = make_float4(0.f, 0.f, 0.f, 0.f);
    int i = q * 4;
    if (i < 32768) {
#pragma unroll
        for (int u = 0; u < 4; u++) {
            int ii = i + u;
            int k = ii >> 8, j = ii & 255;
            float v = (j < 128) ? Wl2[k * 128 + j] : Wr2[k * 128 + j - 128];
            w2[ii] = __float2half_rn(v);
        }
    } else if (i < 40960) {
#pragma unroll
        for (int u = 0; u < 4; u++) {
            int qq = i + u - 32768;
            int k = qq >> 6, j = qq & 63;
            float v = (j < 32) ? Wl3[k * 32 + j] : Wr3[k * 32 + j - 32];
            w3[qq] = __float2half_rn(v);
        }
    } else if (i < 43008) {
#pragma unroll
        for (int u = 0; u < 4; u++) {
            int qq = i + u - 40960;
            int k = qq >> 6, j = qq & 63;
            float v = (j < 32) ? Wl4[k * 32 + j] : Wr4[k * 32 + j - 32];
            w4[qq] = __float2half_rn(v);
        }
    } else if (i < 45056) {
#pragma unroll
        for (int u = 0; u < 4; u++) {
            int qq = i + u - 43008;
            int k = qq >> 6, j = qq & 63;
            float v = (j < 32) ? Wl5[k * 32 + j] : Wr5[k * 32 + j - 32];
            w5[qq] = __float2half_rn(v);
        }
    }
}

// ---------------- decoupled-lookback exclusive scan (re-zeroes cnt) ----------------
__global__ void k_scan_lb(int* __restrict__ cnt, volatile unsigned* state,
                          int* __restrict__ rowptr, int* __restrict__ cursor, int n) {
    __shared__ int ws[8];
    __shared__ int s_pref;
    GRID_WAIT();
    int bid = blockIdx.x;
    int base = bid * 1024 + threadIdx.x * 4;
    int c[4];
#pragma unroll
    for (int q = 0; q < 4; q++) { int idx = base + q; c[q] = (idx < n) ? cnt[idx] : 0; }
#pragma unroll
    for (int q = 0; q < 4; q++) { int idx = base + q; if (idx < n) cnt[idx] = 0; }
    int s1 = c[0], s2 = s1 + c[1], s3 = s2 + c[2], s4 = s3 + c[3];
    int lane = threadIdx.x & 31, w = threadIdx.x >> 5;
    int v = s4;
#pragma unroll
    for (int d = 1; d < 32; d <<= 1) {
        int u = __shfl_up_sync(0xffffffffu, v, d);
        if (lane >= d) v += u;
    }
    int texcl = v - s4;
    if (lane == 31) ws[w] = v;
    __syncthreads();
    if (threadIdx.x == 0) {
        int run = 0;
#pragma unroll
        for (int i = 0; i < 8; i++) { int t = ws[i]; ws[i] = run; run += t; }
        if (bid == 0) {
            state[0] = ((unsigned)run << 2) | 2u;
            __threadfence();
            s_pref = 0;
        } else {
            state[bid] = ((unsigned)run << 2) | 1u;
            __threadfence();
            int pref = 0;
            int j = bid - 1;
            while (true) {
                unsigned st = state[j];
                unsigned mode = st & 3u;
                if (mode == 0u) { __nanosleep(20); continue; }
                pref += (int)(st >> 2);
                if (mode == 2u) break;
                j--;
            }
            state[bid] = ((unsigned)(pref + run) << 2) | 2u;
            __threadfence();
            s_pref = pref;
        }
    }
    __syncthreads();
    int ofs = s_pref + ws[w] + texcl;
    int sv[4] = {s1, s2, s3, s4};
#pragma unroll
    for (int q = 0; q < 4; q++) {
        int idx = base + q;
        if (idx < n) {
            int val = ofs + sv[q];
            rowptr[idx + 1] = val;
            cursor[idx] = val - c[q];
        }
    }
    if (bid == 0 && threadIdx.x == 0) rowptr[0] = 0;
}

// ---------------- fill CSR (vectorized) + layer-1 aggregation ----------------
__global__ void k_fill(const int* __restrict__ ei, const float* __restrict__ x,
                       int* __restrict__ cursor, int* __restrict__ csrc,
                       float* __restrict__ aggx, int E) {
    int q = blockIdx.x * blockDim.x + threadIdx.x;
    int e = q * 4;
    GRID_WAIT();
    if (e + 3 < E) {
        uint4 s4v = *(const uint4*)&ei[e];
        uint4 d4v = *(const uint4*)&ei[E + e];
        int ss[4] = {(int)s4v.x, (int)s4v.y, (int)s4v.z, (int)s4v.w};
        int dd[4] = {(int)d4v.x, (int)d4v.y, (int)d4v.z, (int)d4v.w};
#pragma unroll
        for (int u = 0; u < 4; u++) {
            int p = atomicAdd(&cursor[dd[u]], 1);
            csrc[p] = ss[u];
            float2 xv = *(const float2*)&x[2 * ss[u]];
            atomicAdd(&aggx[2 * dd[u]], xv.x);
            atomicAdd(&aggx[2 * dd[u] + 1], xv.y);
        }
    } else {
        for (int t = e; t < E; t++) {
            int s = ei[t], d = ei[E + t];
            int p = atomicAdd(&cursor[d], 1);
            csrc[p] = s;
            float2 xv = *(const float2*)&x[2 * s];
            atomicAdd(&aggx[2 * d], xv.x);
            atomicAdd(&aggx[2 * d + 1], xv.y);
        }
    }
}

// ---------------- layer 1 register-weight ----------------
__launch_bounds__(256, 8)
__global__ void k_layer1r(const float* __restrict__ x, const float* __restrict__ aggx,
                          const int* __restrict__ rowptr,
                          const float* __restrict__ Wl, const float* __restrict__ bl,
                          const float* __restrict__ Wr,
                          __half* __restrict__ hout, int n) {
    __shared__ float4 sRF[64];
    int tid = threadIdx.x;
    int node0 = blockIdx.x * 64;
    int cp = tid & 63;
    int nl = tid >> 6;
    int j = cp * 2;
    float2 wl0 = *(const float2*)&Wl[j];
    float2 wl1 = *(const float2*)&Wl[128 + j];
    float2 wr0 = *(const float2*)&Wr[j];
    float2 wr1 = *(const float2*)&Wr[128 + j];
    float2 bb  = *(const float2*)&bl[j];
    GRID_WAIT();
    if (tid < 64) {
        int node = node0 + tid;
        float4 rf = make_float4(0.f, 0.f, 0.f, 0.f);
        if (node < n) {
            float deg = (float)(rowptr[node + 1] - rowptr[node]);
            float inv = 1.0f / fmaxf(deg, 1.0f);
            rf.x = aggx[2 * node] * inv;
            rf.y = aggx[2 * node + 1] * inv;
            float2 xv = *(const float2*)&x[2 * node];
            rf.z = xv.x; rf.w = xv.y;
        }
        sRF[tid] = rf;
    }
    __syncthreads();
    int lim = n - node0;
    if (lim > 64) lim = 64;
#pragma unroll 4
    for (int nn = nl; nn < lim; nn += 4) {
        float4 rf = sRF[nn];
        float oa = fmaxf(bb.x + rf.x * wl0.x + rf.y * wl1.x + rf.z * wr0.x + rf.w * wr1.x, 0.f);
        float ob = fmaxf(bb.y + rf.x * wl0.y + rf.y * wl1.y + rf.z * wr0.y + rf.w * wr1.y, 0.f);
        __half2 p = __floats2half2_rn(oa, ob);
        *(__half2*)&hout[(node0 + nn) * 128 + j] = p;
    }
}

// ---------------- layer-2 GEMM: split-N, 2 CTAs/SM, cp.async, PDL prelude on B ----------
__launch_bounds__(512, 2)
__global__ void k_gemm2(const __half* __restrict__ A, const __half* __restrict__ W,
                        __half* __restrict__ Cl, __half* __restrict__ Cr, int n) {
    constexpr int K = 128;
    constexpr int LDA = 136, LDB = 136;
    extern __shared__ __half sm[];
    __half* As = sm;
    __half* Bs = sm + 128 * LDA;
    int tid = threadIdx.x;
    int row0 = blockIdx.x * 128;
    int nh = blockIdx.y;

    for (int i = tid; i < K * 128 / 8; i += 512) {
        int f = i * 8;
        int k = f >> 7, j = f & 127;
        cp16(smem_u32(&Bs[k * LDB + j]), &W[k * 256 + nh * 128 + j]);
    }
    GRID_WAIT();
    int full_rows = n - row0;
    if (full_rows >= 128) {
        for (int i = tid; i < 128 * K / 8; i += 512) {
            int f = i * 8;
            int m = f >> 7, k = f & 127;
            cp16(smem_u32(&As[m * LDA + k]), &A[(row0 + m) * K + k]);
        }
        cp_commit_wait();
    } else {
        cp_commit_wait();
        for (int i = tid; i < 128 * K / 8; i += 512) {
            int f = i * 8;
            int m = f >> 7, k = f & 127;
            int row = row0 + m;
            uint4 v = make_uint4(0u, 0u, 0u, 0u);
            if (row < n) v = *(const uint4*)&A[row * K + k];
            *(uint4*)&As[m * LDA + k] = v;
        }
    }
    __syncthreads();

    int wid = tid >> 5, lane = tid & 31;
    int wm = wid & 3, wn = wid >> 2;
    int m_base = wm * 32, n_base = wn * 32;

    float acc[2][4][4];
#pragma unroll
    for (int im = 0; im < 2; im++)
#pragma unroll
        for (int jn = 0; jn < 4; jn++)
#pragma unroll
            for (int q = 0; q < 4; q++) acc[im][jn][q] = 0.f;

    int lr = lane & 15, lc = lane >> 4;
    uint32_t a_base0 = smem_u32(&As[(m_base + lr) * LDA]);
    uint32_t a_base1 = smem_u32(&As[(m_base + 16 + lr) * LDA]);
    uint32_t b_base4 = smem_u32(&Bs[lr * LDB + n_base + (lc << 3)]);

#pragma unroll
    for (int k0 = 0; k0 < K; k0 += 16) {
        uint32_t af[2][4];
        ldsm_x4(af[0][0], af[0][1], af[0][2], af[0][3], a_base0 + (k0 + lc * 8) * 2);
        ldsm_x4(af[1][0], af[1][1], af[1][2], af[1][3], a_base1 + (k0 + lc * 8) * 2);
        uint32_t bf[4][2];
        ldsm_x4t(bf[0][0], bf[0][1], bf[1][0], bf[1][1], b_base4 + (k0 * LDB) * 2);
        ldsm_x4t(bf[2][0], bf[2][1], bf[3][0], bf[3][1], b_base4 + (k0 * LDB + 16) * 2);
#pragma unroll
        for (int im = 0; im < 2; im++)
#pragma unroll
            for (int jn = 0; jn < 4; jn++)
                mma16816(acc[im][jn], af[im][0], af[im][1], af[im][2], af[im][3],
                         bf[jn][0], bf[jn][1]);
    }

    __half* C = nh ? Cr : Cl;
    int quad = lane >> 2, t4 = lane & 3;
#pragma unroll
    for (int im = 0; im < 2; im++) {
#pragma unroll
        for (int jn = 0; jn < 4; jn++) {
            int col = n_base + jn * 8 + t4 * 2;
            int r0 = row0 + m_base + im * 16 + quad;
            int r1 = r0 + 8;
            if (r0 < n) {
                __half2 h = __floats2half2_rn(acc[im][jn][0], acc[im][jn][1]);
                *(__half2*)&C[r0 * 128 + col] = h;
            }
            if (r1 < n) {
                __half2 h = __floats2half2_rn(acc[im][jn][2], acc[im][jn][3]);
                *(__half2*)&C[r1 * 128 + col] = h;
            }
        }
    }
}

// ---------------- gather accumulate macros ----------------
#define ACC8(v)                                              \
    do {                                                     \
        float2 _f;                                           \
        _f = __half22float2(*(__half2*)&(v).x); a0 += _f.x; a1 += _f.y; \
        _f = __half22float2(*(__half2*)&(v).y); a2 += _f.x; a3 += _f.y; \
        _f = __half22float2(*(__half2*)&(v).z); a4 += _f.x; a5 += _f.y; \
        _f = __half22float2(*(__half2*)&(v).w); a6 += _f.x; a7 += _f.y; \
    } while (0)

#define ACC8B(v)                                             \
    do {                                                     \
        float2 _f;                                           \
        _f = __half22float2(*(__half2*)&(v).x); c0 += _f.x; c1 += _f.y; \
        _f = __half22float2(*(__half2*)&(v).y); c2 += _f.x; c3 += _f.y; \
        _f = __half22float2(*(__half2*)&(v).z); c4 += _f.x; c5 += _f.y; \
        _f = __half22float2(*(__half2*)&(v).w); c6 += _f.x; c7 += _f.y; \
    } while (0)

// ---------------- fused post(D=128) + GEMM3 (128 -> 32|32) ----------------
// 512 threads, 64 nodes/block, 8 lanes/node (16 cols each). 2 CTAs/SM.
__launch_bounds__(512, 2)
__global__ void k_pg128(const int* __restrict__ rowptr, const int* __restrict__ csrc,
                        const __half* __restrict__ hl, const __half* __restrict__ hr,
                        const float* __restrict__ bl, const __half* __restrict__ w,
                        __half* __restrict__ outl, __half* __restrict__ outr, int n) {
    constexpr int LDH = 136;
    constexpr int LDB = 72;
    __shared__ __half hT[64 * LDH];     // 17408 B
    __shared__ __half Bs[128 * LDB];    // 18432 B
    int tid = threadIdx.x;
    int node0 = blockIdx.x * 64;

    // prelude: W3 [128][64] (written by k_count, transitively complete)
    for (int i = tid; i < 1024; i += 512) {
        int f = i * 8;
        int k = f >> 6, j = f & 63;
        *(uint4*)&Bs[k * LDB + j] = *(const uint4*)&w[f];
    }
    GRID_WAIT();

    int local = tid >> 3;
    int sub = tid & 7;
    int node = node0 + local;
    int cbase = sub * 16;
    uint4 ova = make_uint4(0u, 0u, 0u, 0u);
    uint4 ovb = make_uint4(0u, 0u, 0u, 0u);
    if (node < n) {
        int rs = rowptr[node], re = rowptr[node + 1];
        float a0=0.f,a1=0.f,a2=0.f,a3=0.f,a4=0.f,a5=0.f,a6=0.f,a7=0.f;
        float c0=0.f,c1=0.f,c2=0.f,c3=0.f,c4=0.f,c5=0.f,c6=0.f,c7=0.f;
        int t = rs;
        for (; t + 1 < re; t += 2) {
            int s0 = csrc[t], s1 = csrc[t + 1];
            uint4 va0 = *(const uint4*)&hl[s0 * 128 + cbase];
            uint4 vb0 = *(const uint4*)&hl[s0 * 128 + cbase + 8];
            uint4 va1 = *(const uint4*)&hl[s1 * 128 + cbase];
            uint4 vb1 = *(const uint4*)&hl[s1 * 128 + cbase + 8];
            ACC8(va0); ACC8B(vb0); ACC8(va1); ACC8B(vb1);
        }
        if (t < re) {
            int s0 = csrc[t];
            uint4 va0 = *(const uint4*)&hl[s0 * 128 + cbase];
            uint4 vb0 = *(const uint4*)&hl[s0 * 128 + cbase + 8];
            ACC8(va0); ACC8B(vb0);
        }
        float inv = 1.0f / fmaxf((float)(re - rs), 1.0f);
        uint4 rva = *(const uint4*)&hr[node * 128 + cbase];
        uint4 rvb = *(const uint4*)&hr[node * 128 + cbase + 8];
        float4 b0 = *(const float4*)&bl[cbase];
        float4 b1 = *(const float4*)&bl[cbase + 4];
        float4 b2 = *(const float4*)&bl[cbase + 8];
        float4 b3 = *(const float4*)&bl[cbase + 12];
        float2 r01 = __half22float2(*(__half2*)&rva.x);
        float2 r23 = __half22float2(*(__half2*)&rva.y);
        float2 r45 = __half22float2(*(__half2*)&rva.z);
        float2 r67 = __half22float2(*(__half2*)&rva.w);
        __half2 p0 = __floats2half2_rn(fmaxf(a0 * inv + b0.x + r01.x, 0.f), fmaxf(a1 * inv + b0.y + r01.y, 0.f));
        __half2 p1 = __floats2half2_rn(fmaxf(a2 * inv + b0.z + r23.x, 0.f), fmaxf(a3 * inv + b0.w + r23.y, 0.f));
        __half2 p2 = __floats2half2_rn(fmaxf(a4 * inv + b1.x + r45.x, 0.f), fmaxf(a5 * inv + b1.y + r45.y, 0.f));
        __half2 p3 = __floats2half2_rn(fmaxf(a6 * inv + b1.z + r67.x, 0.f), fmaxf(a7 * inv + b1.w + r67.y, 0.f));
        ova.x = *(unsigned*)&p0; ova.y = *(unsigned*)&p1;
        ova.z = *(unsigned*)&p2; ova.w = *(unsigned*)&p3;
        float2 q01 = __half22float2(*(__half2*)&rvb.x);
        float2 q23 = __half22float2(*(__half2*)&rvb.y);
        float2 q45 = __half22float2(*(__half2*)&rvb.z);
        float2 q67 = __half22float2(*(__half2*)&rvb.w);
        __half2 q0 = __floats2half2_rn(fmaxf(c0 * inv + b2.x + q01.x, 0.f), fmaxf(c1 * inv + b2.y + q01.y, 0.f));
        __half2 q1 = __floats2half2_rn(fmaxf(c2 * inv + b2.z + q23.x, 0.f), fmaxf(c3 * inv + b2.w + q23.y, 0.f));
        __half2 q2 = __floats2half2_rn(fmaxf(c4 * inv + b3.x + q45.x, 0.f), fmaxf(c5 * inv + b3.y + q45.y, 0.f));
        __half2 q3 = __floats2half2_rn(fmaxf(c6 * inv + b3.z + q67.x, 0.f), fmaxf(c7 * inv + b3.w + q67.y, 0.f));
        ovb.x = *(unsigned*)&q0; ovb.y = *(unsigned*)&q1;
        ovb.z = *(unsigned*)&q2; ovb.w = *(unsigned*)&q3;
    }
    *(uint4*)&hT[local * LDH + cbase] = ova;
    *(uint4*)&hT[local * LDH + cbase + 8] = ovb;
    __syncthreads();

    // GEMM phase: 16 warps, warp tile 16x16, K=128
    int wid = tid >> 5, lane = tid & 31;
    int wm = wid & 3, wn = wid >> 2;
    int m0 = wm * 16, n0 = wn * 16;
    float acc[2][4];
#pragma unroll
    for (int jn = 0; jn < 2; jn++)
#pragma unroll
        for (int q = 0; q < 4; q++) acc[jn][q] = 0.f;
    int lr = lane & 15, lc = lane >> 4;
    uint32_t a_base = smem_u32(&hT[(m0 + lr) * LDH]);
    uint32_t b4 = smem_u32(&Bs[lr * LDB + n0 + (lc << 3)]);
#pragma unroll
    for (int k0 = 0; k0 < 128; k0 += 16) {
        uint32_t a0, a1, a2, a3;
        ldsm_x4(a0, a1, a2, a3, a_base + (k0 + lc * 8) * 2);
        uint32_t bf[2][2];
        ldsm_x4t(bf[0][0], bf[0][1], bf[1][0], bf[1][1], b4 + (k0 * LDB) * 2);
        mma16816(acc[0], a0, a1, a2, a3, bf[0][0], bf[0][1]);
        mma16816(acc[1], a0, a1, a2, a3, bf[1][0], bf[1][1]);
    }
    int quad = lane >> 2, t4 = lane & 3;
#pragma unroll
    for (int jn = 0; jn < 2; jn++) {
        int col = n0 + jn * 8 + t4 * 2;
        int r0 = node0 + m0 + quad, r1 = r0 + 8;
        __half* C; int cc;
        if (col < 32) { C = outl; cc = col; } else { C = outr; cc = col - 32; }
        if (r0 < n) *(__half2*)&C[r0 * 32 + cc] = __floats2half2_rn(acc[jn][0], acc[jn][1]);
        if (r1 < n) *(__half2*)&C[r1 * 32 + cc] = __floats2half2_rn(acc[jn][2], acc[jn][3]);
    }
}

// ---------------- fused post(D=32) + GEMM (32 -> 32|32), PDL prelude on Bs ---------------
__launch_bounds__(256, 6)
__global__ void k_pg32(const int* __restrict__ rowptr, const int* __restrict__ csrc,
                       const __half* __restrict__ hl, const __half* __restrict__ hr,
                       const float* __restrict__ bl, const __half* __restrict__ w,
                       __half* __restrict__ outl, __half* __restrict__ outr, int n) {
    constexpr int LDH = 40;
    constexpr int LDB = 72;
    __shared__ __half hT[64 * LDH];
    __shared__ __half Bs[32 * LDB];
    int tid = threadIdx.x;
    int node0 = blockIdx.x * 64;

    {
        int f = tid * 8;
        int k = f >> 6, j = f & 63;
        *(uint4*)&Bs[k * LDB + j] = *(const uint4*)&w[f];
    }
    GRID_WAIT();

    int local = tid >> 2;
    int sub = tid & 3;
    int node = node0 + local;
    uint4 ov = make_uint4(0u, 0u, 0u, 0u);
    if (node < n) {
        int rs = rowptr[node], re = rowptr[node + 1];
        float a0 = 0.f, a1 = 0.f, a2 = 0.f, a3 = 0.f, a4 = 0.f, a5 = 0.f, a6 = 0.f, a7 = 0.f;
        int t = rs;
        for (; t + 3 < re; t += 4) {
            int s0 = csrc[t], s1 = csrc[t + 1], s2 = csrc[t + 2], s3 = csrc[t + 3];
            uint4 v0 = *(const uint4*)&hl[s0 * 32 + sub * 8];
            uint4 v1 = *(const uint4*)&hl[s1 * 32 + sub * 8];
            uint4 v2 = *(const uint4*)&hl[s2 * 32 + sub * 8];
            uint4 v3 = *(const uint4*)&hl[s3 * 32 + sub * 8];
            ACC8(v0); ACC8(v1); ACC8(v2); ACC8(v3);
        }
        for (; t < re; t++) {
            int s0 = csrc[t];
            uint4 v0 = *(const uint4*)&hl[s0 * 32 + sub * 8];
            ACC8(v0);
        }
        float inv = 1.0f / fmaxf((float)(re - rs), 1.0f);
        uint4 rv = *(const uint4*)&hr[node * 32 + sub * 8];
        float2 r01 = __half22float2(*(__half2*)&rv.x);
        float2 r23 = __half22float2(*(__half2*)&rv.y);
        float2 r45 = __half22float2(*(__half2*)&rv.z);
        float2 r67 = __half22float2(*(__half2*)&rv.w);
        float4 b0 = *(const float4*)&bl[sub * 8];
        float4 b1 = *(const float4*)&bl[sub * 8 + 4];
        __half2 p0 = __floats2half2_rn(fmaxf(a0 * inv + b0.x + r01.x, 0.f), fmaxf(a1 * inv + b0.y + r01.y, 0.f));
        __half2 p1 = __floats2half2_rn(fmaxf(a2 * inv + b0.z + r23.x, 0.f), fmaxf(a3 * inv + b0.w + r23.y, 0.f));
        __half2 p2 = __floats2half2_rn(fmaxf(a4 * inv + b1.x + r45.x, 0.f), fmaxf(a5 * inv + b1.y + r45.y, 0.f));
        __half2 p3 = __floats2half2_rn(fmaxf(a6 * inv + b1.z + r67.x, 0.f), fmaxf(a7 * inv + b1.w + r67.y, 0.f));
        ov.x = *(unsigned*)&p0; ov.y = *(unsigned*)&p1;
        ov.z = *(unsigned*)&p2; ov.w = *(unsigned*)&p3;
    }
    *(uint4*)&hT[local * LDH + sub * 8] = ov;
    __syncthreads();

    int wid = tid >> 5, lane = tid & 31;
    int wm = wid & 3, wn = wid >> 2;
    int m0 = wm * 16, n0 = wn * 32;
    float acc[4][4];
#pragma unroll
    for (int jn = 0; jn < 4; jn++)
#pragma unroll
        for (int q = 0; q < 4; q++) acc[jn][q] = 0.f;
    int lr = lane & 15, lc = lane >> 4;
    uint32_t a_base = smem_u32(&hT[(m0 + lr) * LDH]);
    uint32_t b4 = smem_u32(&Bs[lr * LDB + n0 + (lc << 3)]);
#pragma unroll
    for (int k0 = 0; k0 < 32; k0 += 16) {
        uint32_t a0, a1, a2, a3;
        ldsm_x4(a0, a1, a2, a3, a_base + (k0 + lc * 8) * 2);
        uint32_t bf[4][2];
        ldsm_x4t(bf[0][0], bf[0][1], bf[1][0], bf[1][1], b4 + (k0 * LDB) * 2);
        ldsm_x4t(bf[2][0], bf[2][1], bf[3][0], bf[3][1], b4 + (k0 * LDB + 16) * 2);
#pragma unroll
        for (int jn = 0; jn < 4; jn++)
            mma16816(acc[jn], a0, a1, a2, a3, bf[jn][0], bf[jn][1]);
    }
    int quad = lane >> 2, t4 = lane & 3;
#pragma unroll
    for (int jn = 0; jn < 4; jn++) {
        int col = n0 + jn * 8 + t4 * 2;
        int r0 = node0 + m0 + quad, r1 = r0 + 8;
        __half* C; int cc;
        if (col < 32) { C = outl; cc = col; } else { C = outr; cc = col - 32; }
        if (r0 < n) *(__half2*)&C[r0 * 32 + cc] = __floats2half2_rn(acc[jn][0], acc[jn][1]);
        if (r1 < n) *(__half2*)&C[r1 * 32 + cc] = __floats2half2_rn(acc[jn][2], acc[jn][3]);
    }
}

// ---------------- layer 5 post fused with output head ----------------
__global__ void k_post_out(const int* __restrict__ rowptr, const int* __restrict__ csrc,
                           const __half* __restrict__ hl, const __half* __restrict__ hr,
                           const float* __restrict__ bl,
                           const float* __restrict__ Wo, const float* __restrict__ bo,
                           float* __restrict__ out, int n) {
    constexpr int D = 32;
    constexpr int LPN = 4;
    int tid = blockIdx.x * blockDim.x + threadIdx.x;
    int node = tid / LPN;
    int sub = tid % LPN;
    GRID_WAIT();
    if (node >= n) return;
    int rs = rowptr[node], re = rowptr[node + 1];
    float a0 = 0.f, a1 = 0.f, a2 = 0.f, a3 = 0.f, a4 = 0.f, a5 = 0.f, a6 = 0.f, a7 = 0.f;
    int t = rs;
    for (; t + 3 < re; t += 4) {
        int s0 = csrc[t], s1 = csrc[t + 1], s2 = csrc[t + 2], s3 = csrc[t + 3];
        uint4 v0 = *(const uint4*)&hl[s0 * D + sub * 8];
        uint4 v1 = *(const uint4*)&hl[s1 * D + sub * 8];
        uint4 v2 = *(const uint4*)&hl[s2 * D + sub * 8];
        uint4 v3 = *(const uint4*)&hl[s3 * D + sub * 8];
        ACC8(v0); ACC8(v1); ACC8(v2); ACC8(v3);
    }
    for (; t < re; t++) {
        int s0 = csrc[t];
        uint4 v0 = *(const uint4*)&hl[s0 * D + sub * 8];
        ACC8(v0);
    }
    float dv = (float)(re - rs);
    float inv = 1.0f / fmaxf(dv, 1.0f);
    uint4 rv = *(const uint4*)&hr[node * D + sub * 8];
    float2 r01 = __half22float2(*(__half2*)&rv.x);
    float2 r23 = __half22float2(*(__half2*)&rv.y);
    float2 r45 = __half22float2(*(__half2*)&rv.z);
    float2 r67 = __half22float2(*(__half2*)&rv.w);
    float4 b0 = *(const float4*)&bl[sub * 8];
    float4 b1 = *(const float4*)&bl[sub * 8 + 4];
    float4 w0 = *(const float4*)&Wo[sub * 8];
    float4 w1 = *(const float4*)&Wo[sub * 8 + 4];
    float s = 0.f;
    s += fmaxf(a0 * inv + b0.x + r01.x, 0.f) * w0.x;
    s += fmaxf(a1 * inv + b0.y + r01.y, 0.f) * w0.y;
    s += fmaxf(a2 * inv + b0.z + r23.x, 0.f) * w0.z;
    s += fmaxf(a3 * inv + b0.w + r23.y, 0.f) * w0.w;
    s += fmaxf(a4 * inv + b1.x + r45.x, 0.f) * w1.x;
    s += fmaxf(a5 * inv + b1.y + r45.y, 0.f) * w1.y;
    s += fmaxf(a6 * inv + b1.z + r67.x, 0.f) * w1.z;
    s += fmaxf(a7 * inv + b1.w + r67.y, 0.f) * w1.w;
    s += __shfl_xor_sync(0xffffffffu, s, 1);
    s += __shfl_xor_sync(0xffffffffu, s, 2);
    if (sub == 0) out[node] = s + bo[0];
}

// ---------------- PDL launch helper ----------------
template <typename F, typename... Args>
static void launch_pdl(F f, dim3 grid, dim3 block, size_t smem, Args... args) {
    cudaLaunchConfig_t cfg = {};
    cfg.gridDim = grid;
    cfg.blockDim = block;
    cfg.dynamicSmemBytes = smem;
    cfg.stream = 0;
    cudaLaunchAttribute attr[1];
    attr[0].id = cudaLaunchAttributeProgrammaticStreamSerialization;
    attr[0].val.programmaticStreamSerializationAllowed = 1;
    cfg.attrs = attr;
    cfg.numAttrs = 1;
    cudaLaunchKernelEx(&cfg, f, args...);
}

// ---------------- launch ----------------
extern "C" void kernel_launch(void* const* d_in, const int* in_sizes, int n_in,
                              void* d_out, int out_size) {
    const float* x   = (const float*)d_in[0];
    const int*   ei  = (const int*)d_in[1];
    const float* Wl1 = (const float*)d_in[3];
    const float* bl1 = (const float*)d_in[4];
    const float* Wr1 = (const float*)d_in[5];
    const float* Wl2 = (const float*)d_in[6];
    const float* bl2 = (const float*)d_in[7];
    const float* Wr2 = (const float*)d_in[8];
    const float* Wl3 = (const float*)d_in[9];
    const float* bl3 = (const float*)d_in[10];
    const float* Wr3 = (const float*)d_in[11];
    const float* Wl4 = (const float*)d_in[12];
    const float* bl4 = (const float*)d_in[13];
    const float* Wr4 = (const float*)d_in[14];
    const float* Wl5 = (const float*)d_in[15];
    const float* bl5 = (const float*)d_in[16];
    const float* Wr5 = (const float*)d_in[17];
    const float* Wo  = (const float*)d_in[18];
    const float* bo  = (const float*)d_in[19];
    float* out = (float*)d_out;

    int n = in_sizes[0] / 2;
    int E = in_sizes[1] / 2;

    __half *p_h, *p_hl, *p_hr, *p_w2, *p_w3, *p_w4, *p_w5;
    float* p_aggx;
    int *p_cnt, *p_rowptr, *p_cursor, *p_csrc;
    unsigned* p_state;
    cudaGetSymbolAddress((void**)&p_h, g_h);
    cudaGetSymbolAddress((void**)&p_hl, g_hl);
    cudaGetSymbolAddress((void**)&p_hr, g_hr);
    cudaGetSymbolAddress((void**)&p_aggx, g_aggx);
    cudaGetSymbolAddress((void**)&p_w2, g_w2);
    cudaGetSymbolAddress((void**)&p_w3, g_w3);
    cudaGetSymbolAddress((void**)&p_w4, g_w4);
    cudaGetSymbolAddress((void**)&p_w5, g_w5);
    cudaGetSymbolAddress((void**)&p_cnt, g_cnt);
    cudaGetSymbolAddress((void**)&p_rowptr, g_rowptr);
    cudaGetSymbolAddress((void**)&p_cursor, g_cursor);
    cudaGetSymbolAddress((void**)&p_csrc, g_csrc);
    cudaGetSymbolAddress((void**)&p_state, g_state);

    cudaFuncSetAttribute(k_gemm2, cudaFuncAttributeMaxDynamicSharedMemorySize, 69632);

    int NB = (n + 1023) / 1024;
    int eq = ((E + 3) / 4 + 255) / 256;
    int gb = (n + 127) / 128;
    int g_l1 = (n + 63) / 64;
    int g_64 = (n + 63) / 64;
    int g_4  = (n * 4 + 255) / 256;

    __half* hA = p_h;
    __half* hB = p_h + NN * 32;

    // CSR build (first launch plain; rest PDL-marked)
    k_count<<<eq, 256>>>(ei, p_cnt, E, Wl2, Wr2, Wl3, Wr3, Wl4, Wr4, Wl5, Wr5,
                         p_w2, p_w3, p_w4, p_w5, p_state, p_aggx, n);
    launch_pdl(k_scan_lb, dim3(NB), dim3(256), 0, p_cnt, (volatile unsigned*)p_state, p_rowptr, p_cursor, n);
    launch_pdl(k_fill, dim3(eq), dim3(256), 0, ei, x, p_cursor, p_csrc, p_aggx, E);

    // layer 1 (2 -> 128)
    launch_pdl(k_layer1r, dim3(g_l1), dim3(256), 0, x, p_aggx, p_rowptr, Wl1, bl1, Wr1, p_h, n);

    // layer 2 (128 -> 128)
    launch_pdl(k_gemm2, dim3(gb, 2), dim3(512), (size_t)69632,
               (const __half*)p_h, (const __half*)p_w2, p_hl, p_hr, n);

    // post(layer2) + GEMM3 fused -> hl3 in hA, hr3 in hB
    launch_pdl(k_pg128, dim3(g_64), dim3(512), 0,
               (const int*)p_rowptr, (const int*)p_csrc, (const __half*)p_hl, (const __half*)p_hr,
               bl2, (const __half*)p_w3, hA, hB, n);

    // post(layer3) + GEMM4 -> p_hl, p_hr
    launch_pdl(k_pg32, dim3(g_64), dim3(256), 0,
               (const int*)p_rowptr, (const int*)p_csrc, (const __half*)hA, (const __half*)hB,
               bl3, (const __half*)p_w4, p_hl, p_hr, n);

    // post(layer4) + GEMM5 -> hA, hB
    launch_pdl(k_pg32, dim3(g_64), dim3(256), 0,
               (const int*)p_rowptr, (const int*)p_csrc, (const __half*)p_hl, (const __half*)p_hr,
               bl4, (const __half*)p_w5, hA, hB, n);

    // post(layer5) + output head
    launch_pdl(k_post_out, dim3(g_4), dim3(256), 0,
               (const int*)p_rowptr, (const int*)p_csrc, (const __half*)hA, (const __half*)hB,
               bl5, Wo, bo, out, n);
}

// round 17
// speedup vs baseline: 1.0337x; 1.0337x over previous
#include <cuda_runtime.h>
#include <cuda_fp16.h>
#include <cstdint>

#define NN 100000
#define NE 1600000

#define GRID_WAIT() asm volatile("griddepcontrol.wait;" ::: "memory")

// ---------------- scratch ----------------
__device__ __half g_h [NN * 128];
__device__ __half g_hl[NN * 128];
__device__ __half g_hr[NN * 128];
__device__ float  g_aggx[2 * NN];
__device__ __half g_w2[128 * 256];
__device__ __half g_w3[128 * 64];
__device__ __half g_w4[32 * 64];
__device__ __half g_w5[32 * 64];
__device__ int    g_cnt[NN];        // zero-init at load; k_scan_lb re-zeroes after use
__device__ int    g_rowptr[NN + 1];
__device__ int    g_cursor[NN];
__device__ int    g_csrc[NE];
__device__ unsigned g_state[128];

// ---------------- mma / async helpers ----------------
__device__ __forceinline__ uint32_t smem_u32(const void* p) {
    return (uint32_t)__cvta_generic_to_shared(p);
}
__device__ __forceinline__ void cp16(uint32_t dst, const void* src) {
    asm volatile("cp.async.cg.shared.global [%0], [%1], 16;" :: "r"(dst), "l"(src));
}
__device__ __forceinline__ void cp_commit_wait() {
    asm volatile("cp.async.commit_group;\ncp.async.wait_group 0;" ::: "memory");
}
__device__ __forceinline__ void ldsm_x4(uint32_t& r0, uint32_t& r1, uint32_t& r2, uint32_t& r3, uint32_t a) {
    asm volatile("ldmatrix.sync.aligned.m8n8.x4.shared.b16 {%0,%1,%2,%3},[%4];"
                 : "=r"(r0), "=r"(r1), "=r"(r2), "=r"(r3) : "r"(a));
}
__device__ __forceinline__ void ldsm_x4t(uint32_t& r0, uint32_t& r1, uint32_t& r2, uint32_t& r3, uint32_t a) {
    asm volatile("ldmatrix.sync.aligned.m8n8.x4.trans.shared.b16 {%0,%1,%2,%3},[%4];"
                 : "=r"(r0), "=r"(r1), "=r"(r2), "=r"(r3) : "r"(a));
}
__device__ __forceinline__ void mma16816(float* c, uint32_t a0, uint32_t a1, uint32_t a2, uint32_t a3,
                                         uint32_t b0, uint32_t b1) {
    asm volatile("mma.sync.aligned.m16n8k16.row.col.f32.f16.f16.f32 "
                 "{%0,%1,%2,%3},{%4,%5,%6,%7},{%8,%9},{%0,%1,%2,%3};"
                 : "+f"(c[0]), "+f"(c[1]), "+f"(c[2]), "+f"(c[3])
                 : "r"(a0), "r"(a1), "r"(a2), "r"(a3), "r"(b0), "r"(b1));
}

// ---------------- count (vectorized) + weight pack + zero state/aggx ----------------
__global__ void k_count(const int* __restrict__ ei, int* __restrict__ cnt, int E,
                        const float* Wl2, const float* Wr2, const float* Wl3, const float* Wr3,
                        const float* Wl4, const float* Wr4, const float* Wl5, const float* Wr5,
                        __half* w2, __half* w3, __half* w4, __half* w5,
                        unsigned* state, float* aggx, int n) {
    int q = blockIdx.x * blockDim.x + threadIdx.x;
    int e = q * 4;
    if (e + 3 < E) {
        uint4 d4 = *(const uint4*)&ei[E + e];
        atomicAdd(&cnt[d4.x], 1);
        atomicAdd(&cnt[d4.y], 1);
        atomicAdd(&cnt[d4.z], 1);
        atomicAdd(&cnt[d4.w], 1);
    } else {
        for (int t = e; t < E; t++) atomicAdd(&cnt[ei[E + t]], 1);
    }
    if (blockIdx.x == 0 && threadIdx.x < 128) state[threadIdx.x] = 0u;
    if (q < (2 * n + 3) / 4) *(float4*)&aggx[q * 4] = make_float4(0.f, 0.f, 0.f, 0.f);
    int i = q * 4;
    if (i < 32768) {
#pragma unroll
        for (int u = 0; u < 4; u++) {
            int ii = i + u;
            int k = ii >> 8, j = ii & 255;
            float v = (j < 128) ? Wl2[k * 128 + j] : Wr2[k * 128 + j - 128];
            w2[ii] = __float2half_rn(v);
        }
    } else if (i < 40960) {
#pragma unroll
        for (int u = 0; u < 4; u++) {
            int qq = i + u - 32768;
            int k = qq >> 6, j = qq & 63;
            float v = (j < 32) ? Wl3[k * 32 + j] : Wr3[k * 32 + j - 32];
            w3[qq] = __float2half_rn(v);
        }
    } else if (i < 43008) {
#pragma unroll
        for (int u = 0; u < 4; u++) {
            int qq = i + u - 40960;
            int k = qq >> 6, j = qq & 63;
            float v = (j < 32) ? Wl4[k * 32 + j] : Wr4[k * 32 + j - 32];
            w4[qq] = __float2half_rn(v);
        }
    } else if (i < 45056) {
#pragma unroll
        for (int u = 0; u < 4; u++) {
            int qq = i + u - 43008;
            int k = qq >> 6, j = qq & 63;
            float v = (j < 32) ? Wl5[k * 32 + j] : Wr5[k * 32 + j - 32];
            w5[qq] = __float2half_rn(v);
        }
    }
}

// ---------------- decoupled-lookback exclusive scan (re-zeroes cnt) ----------------
__global__ void k_scan_lb(int* __restrict__ cnt, volatile unsigned* state,
                          int* __restrict__ rowptr, int* __restrict__ cursor, int n) {
    __shared__ int ws[8];
    __shared__ int s_pref;
    GRID_WAIT();
    int bid = blockIdx.x;
    int base = bid * 1024 + threadIdx.x * 4;
    int c[4];
#pragma unroll
    for (int q = 0; q < 4; q++) { int idx = base + q; c[q] = (idx < n) ? cnt[idx] : 0; }
#pragma unroll
    for (int q = 0; q < 4; q++) { int idx = base + q; if (idx < n) cnt[idx] = 0; }
    int s1 = c[0], s2 = s1 + c[1], s3 = s2 + c[2], s4 = s3 + c[3];
    int lane = threadIdx.x & 31, w = threadIdx.x >> 5;
    int v = s4;
#pragma unroll
    for (int d = 1; d < 32; d <<= 1) {
        int u = __shfl_up_sync(0xffffffffu, v, d);
        if (lane >= d) v += u;
    }
    int texcl = v - s4;
    if (lane == 31) ws[w] = v;
    __syncthreads();
    if (threadIdx.x == 0) {
        int run = 0;
#pragma unroll
        for (int i = 0; i < 8; i++) { int t = ws[i]; ws[i] = run; run += t; }
        if (bid == 0) {
            state[0] = ((unsigned)run << 2) | 2u;
            __threadfence();
            s_pref = 0;
        } else {
            state[bid] = ((unsigned)run << 2) | 1u;
            __threadfence();
            int pref = 0;
            int j = bid - 1;
            while (true) {
                unsigned st = state[j];
                unsigned mode = st & 3u;
                if (mode == 0u) { __nanosleep(20); continue; }
                pref += (int)(st >> 2);
                if (mode == 2u) break;
                j--;
            }
            state[bid] = ((unsigned)(pref + run) << 2) | 2u;
            __threadfence();
            s_pref = pref;
        }
    }
    __syncthreads();
    int ofs = s_pref + ws[w] + texcl;
    int sv[4] = {s1, s2, s3, s4};
#pragma unroll
    for (int q = 0; q < 4; q++) {
        int idx = base + q;
        if (idx < n) {
            int val = ofs + sv[q];
            rowptr[idx + 1] = val;
            cursor[idx] = val - c[q];
        }
    }
    if (bid == 0 && threadIdx.x == 0) rowptr[0] = 0;
}

// ---------------- fill CSR (vectorized, float2 vector atomics) + layer-1 aggregation -----
__global__ void k_fill(const int* __restrict__ ei, const float* __restrict__ x,
                       int* __restrict__ cursor, int* __restrict__ csrc,
                       float2* __restrict__ aggx2, int E) {
    int q = blockIdx.x * blockDim.x + threadIdx.x;
    int e = q * 4;
    GRID_WAIT();
    if (e + 3 < E) {
        uint4 s4v = *(const uint4*)&ei[e];
        uint4 d4v = *(const uint4*)&ei[E + e];
        int ss[4] = {(int)s4v.x, (int)s4v.y, (int)s4v.z, (int)s4v.w};
        int dd[4] = {(int)d4v.x, (int)d4v.y, (int)d4v.z, (int)d4v.w};
#pragma unroll
        for (int u = 0; u < 4; u++) {
            int p = atomicAdd(&cursor[dd[u]], 1);
            csrc[p] = ss[u];
            float2 xv = *(const float2*)&x[2 * ss[u]];
            atomicAdd(&aggx2[dd[u]], xv);        // sm_90+ vector atomic: one op for both comps
        }
    } else {
        for (int t = e; t < E; t++) {
            int s = ei[t], d = ei[E + t];
            int p = atomicAdd(&cursor[d], 1);
            csrc[p] = s;
            float2 xv = *(const float2*)&x[2 * s];
            atomicAdd(&aggx2[d], xv);
        }
    }
}

// ---------------- layer 1 register-weight ----------------
__launch_bounds__(256, 8)
__global__ void k_layer1r(const float* __restrict__ x, const float* __restrict__ aggx,
                          const int* __restrict__ rowptr,
                          const float* __restrict__ Wl, const float* __restrict__ bl,
                          const float* __restrict__ Wr,
                          __half* __restrict__ hout, int n) {
    __shared__ float4 sRF[64];
    int tid = threadIdx.x;
    int node0 = blockIdx.x * 64;
    int cp = tid & 63;
    int nl = tid >> 6;
    int j = cp * 2;
    float2 wl0 = *(const float2*)&Wl[j];
    float2 wl1 = *(const float2*)&Wl[128 + j];
    float2 wr0 = *(const float2*)&Wr[j];
    float2 wr1 = *(const float2*)&Wr[128 + j];
    float2 bb  = *(const float2*)&bl[j];
    GRID_WAIT();
    if (tid < 64) {
        int node = node0 + tid;
        float4 rf = make_float4(0.f, 0.f, 0.f, 0.f);
        if (node < n) {
            float deg = (float)(rowptr[node + 1] - rowptr[node]);
            float inv = 1.0f / fmaxf(deg, 1.0f);
            rf.x = aggx[2 * node] * inv;
            rf.y = aggx[2 * node + 1] * inv;
            float2 xv = *(const float2*)&x[2 * node];
            rf.z = xv.x; rf.w = xv.y;
        }
        sRF[tid] = rf;
    }
    __syncthreads();
    int lim = n - node0;
    if (lim > 64) lim = 64;
#pragma unroll 4
    for (int nn = nl; nn < lim; nn += 4) {
        float4 rf = sRF[nn];
        float oa = fmaxf(bb.x + rf.x * wl0.x + rf.y * wl1.x + rf.z * wr0.x + rf.w * wr1.x, 0.f);
        float ob = fmaxf(bb.y + rf.x * wl0.y + rf.y * wl1.y + rf.z * wr0.y + rf.w * wr1.y, 0.f);
        __half2 p = __floats2half2_rn(oa, ob);
        *(__half2*)&hout[(node0 + nn) * 128 + j] = p;
    }
}

// ---------------- layer-2 GEMM: split-N, 2 CTAs/SM, cp.async, PDL prelude on B ----------
__launch_bounds__(512, 2)
__global__ void k_gemm2(const __half* __restrict__ A, const __half* __restrict__ W,
                        __half* __restrict__ Cl, __half* __restrict__ Cr, int n) {
    constexpr int K = 128;
    constexpr int LDA = 136, LDB = 136;
    extern __shared__ __half sm[];
    __half* As = sm;
    __half* Bs = sm + 128 * LDA;
    int tid = threadIdx.x;
    int row0 = blockIdx.x * 128;
    int nh = blockIdx.y;

    for (int i = tid; i < K * 128 / 8; i += 512) {
        int f = i * 8;
        int k = f >> 7, j = f & 127;
        cp16(smem_u32(&Bs[k * LDB + j]), &W[k * 256 + nh * 128 + j]);
    }
    GRID_WAIT();
    int full_rows = n - row0;
    if (full_rows >= 128) {
        for (int i = tid; i < 128 * K / 8; i += 512) {
            int f = i * 8;
            int m = f >> 7, k = f & 127;
            cp16(smem_u32(&As[m * LDA + k]), &A[(row0 + m) * K + k]);
        }
        cp_commit_wait();
    } else {
        cp_commit_wait();
        for (int i = tid; i < 128 * K / 8; i += 512) {
            int f = i * 8;
            int m = f >> 7, k = f & 127;
            int row = row0 + m;
            uint4 v = make_uint4(0u, 0u, 0u, 0u);
            if (row < n) v = *(const uint4*)&A[row * K + k];
            *(uint4*)&As[m * LDA + k] = v;
        }
    }
    __syncthreads();

    int wid = tid >> 5, lane = tid & 31;
    int wm = wid & 3, wn = wid >> 2;
    int m_base = wm * 32, n_base = wn * 32;

    float acc[2][4][4];
#pragma unroll
    for (int im = 0; im < 2; im++)
#pragma unroll
        for (int jn = 0; jn < 4; jn++)
#pragma unroll
            for (int q = 0; q < 4; q++) acc[im][jn][q] = 0.f;

    int lr = lane & 15, lc = lane >> 4;
    uint32_t a_base0 = smem_u32(&As[(m_base + lr) * LDA]);
    uint32_t a_base1 = smem_u32(&As[(m_base + 16 + lr) * LDA]);
    uint32_t b_base4 = smem_u32(&Bs[lr * LDB + n_base + (lc << 3)]);

#pragma unroll
    for (int k0 = 0; k0 < K; k0 += 16) {
        uint32_t af[2][4];
        ldsm_x4(af[0][0], af[0][1], af[0][2], af[0][3], a_base0 + (k0 + lc * 8) * 2);
        ldsm_x4(af[1][0], af[1][1], af[1][2], af[1][3], a_base1 + (k0 + lc * 8) * 2);
        uint32_t bf[4][2];
        ldsm_x4t(bf[0][0], bf[0][1], bf[1][0], bf[1][1], b_base4 + (k0 * LDB) * 2);
        ldsm_x4t(bf[2][0], bf[2][1], bf[3][0], bf[3][1], b_base4 + (k0 * LDB + 16) * 2);
#pragma unroll
        for (int im = 0; im < 2; im++)
#pragma unroll
            for (int jn = 0; jn < 4; jn++)
                mma16816(acc[im][jn], af[im][0], af[im][1], af[im][2], af[im][3],
                         bf[jn][0], bf[jn][1]);
    }

    __half* C = nh ? Cr : Cl;
    int quad = lane >> 2, t4 = lane & 3;
#pragma unroll
    for (int im = 0; im < 2; im++) {
#pragma unroll
        for (int jn = 0; jn < 4; jn++) {
            int col = n_base + jn * 8 + t4 * 2;
            int r0 = row0 + m_base + im * 16 + quad;
            int r1 = r0 + 8;
            if (r0 < n) {
                __half2 h = __floats2half2_rn(acc[im][jn][0], acc[im][jn][1]);
                *(__half2*)&C[r0 * 128 + col] = h;
            }
            if (r1 < n) {
                __half2 h = __floats2half2_rn(acc[im][jn][2], acc[im][jn][3]);
                *(__half2*)&C[r1 * 128 + col] = h;
            }
        }
    }
}

// ---------------- gather accumulate macros ----------------
#define ACC8(v)                                              \
    do {                                                     \
        float2 _f;                                           \
        _f = __half22float2(*(__half2*)&(v).x); a0 += _f.x; a1 += _f.y; \
        _f = __half22float2(*(__half2*)&(v).y); a2 += _f.x; a3 += _f.y; \
        _f = __half22float2(*(__half2*)&(v).z); a4 += _f.x; a5 += _f.y; \
        _f = __half22float2(*(__half2*)&(v).w); a6 += _f.x; a7 += _f.y; \
    } while (0)

#define ACC8B(v)                                             \
    do {                                                     \
        float2 _f;                                           \
        _f = __half22float2(*(__half2*)&(v).x); c0 += _f.x; c1 += _f.y; \
        _f = __half22float2(*(__half2*)&(v).y); c2 += _f.x; c3 += _f.y; \
        _f = __half22float2(*(__half2*)&(v).z); c4 += _f.x; c5 += _f.y; \
        _f = __half22float2(*(__half2*)&(v).w); c6 += _f.x; c7 += _f.y; \
    } while (0)

// ---------------- fused post(D=128) + GEMM3 (128 -> 32|32) ----------------
__launch_bounds__(512, 2)
__global__ void k_pg128(const int* __restrict__ rowptr, const int* __restrict__ csrc,
                        const __half* __restrict__ hl, const __half* __restrict__ hr,
                        const float* __restrict__ bl, const __half* __restrict__ w,
                        __half* __restrict__ outl, __half* __restrict__ outr, int n) {
    constexpr int LDH = 136;
    constexpr int LDB = 72;
    __shared__ __half hT[64 * LDH];
    __shared__ __half Bs[128 * LDB];
    int tid = threadIdx.x;
    int node0 = blockIdx.x * 64;

    for (int i = tid; i < 1024; i += 512) {
        int f = i * 8;
        int k = f >> 6, j = f & 63;
        *(uint4*)&Bs[k * LDB + j] = *(const uint4*)&w[f];
    }
    GRID_WAIT();

    int local = tid >> 3;
    int sub = tid & 7;
    int node = node0 + local;
    int cbase = sub * 16;
    uint4 ova = make_uint4(0u, 0u, 0u, 0u);
    uint4 ovb = make_uint4(0u, 0u, 0u, 0u);
    if (node < n) {
        int rs = rowptr[node], re = rowptr[node + 1];
        float a0=0.f,a1=0.f,a2=0.f,a3=0.f,a4=0.f,a5=0.f,a6=0.f,a7=0.f;
        float c0=0.f,c1=0.f,c2=0.f,c3=0.f,c4=0.f,c5=0.f,c6=0.f,c7=0.f;
        int t = rs;
        for (; t + 1 < re; t += 2) {
            int s0 = csrc[t], s1 = csrc[t + 1];
            uint4 va0 = *(const uint4*)&hl[s0 * 128 + cbase];
            uint4 vb0 = *(const uint4*)&hl[s0 * 128 + cbase + 8];
            uint4 va1 = *(const uint4*)&hl[s1 * 128 + cbase];
            uint4 vb1 = *(const uint4*)&hl[s1 * 128 + cbase + 8];
            ACC8(va0); ACC8B(vb0); ACC8(va1); ACC8B(vb1);
        }
        if (t < re) {
            int s0 = csrc[t];
            uint4 va0 = *(const uint4*)&hl[s0 * 128 + cbase];
            uint4 vb0 = *(const uint4*)&hl[s0 * 128 + cbase + 8];
            ACC8(va0); ACC8B(vb0);
        }
        float inv = 1.0f / fmaxf((float)(re - rs), 1.0f);
        uint4 rva = *(const uint4*)&hr[node * 128 + cbase];
        uint4 rvb = *(const uint4*)&hr[node * 128 + cbase + 8];
        float4 b0 = *(const float4*)&bl[cbase];
        float4 b1 = *(const float4*)&bl[cbase + 4];
        float4 b2 = *(const float4*)&bl[cbase + 8];
        float4 b3 = *(const float4*)&bl[cbase + 12];
        float2 r01 = __half22float2(*(__half2*)&rva.x);
        float2 r23 = __half22float2(*(__half2*)&rva.y);
        float2 r45 = __half22float2(*(__half2*)&rva.z);
        float2 r67 = __half22float2(*(__half2*)&rva.w);
        __half2 p0 = __floats2half2_rn(fmaxf(a0 * inv + b0.x + r01.x, 0.f), fmaxf(a1 * inv + b0.y + r01.y, 0.f));
        __half2 p1 = __floats2half2_rn(fmaxf(a2 * inv + b0.z + r23.x, 0.f), fmaxf(a3 * inv + b0.w + r23.y, 0.f));
        __half2 p2 = __floats2half2_rn(fmaxf(a4 * inv + b1.x + r45.x, 0.f), fmaxf(a5 * inv + b1.y + r45.y, 0.f));
        __half2 p3 = __floats2half2_rn(fmaxf(a6 * inv + b1.z + r67.x, 0.f), fmaxf(a7 * inv + b1.w + r67.y, 0.f));
        ova.x = *(unsigned*)&p0; ova.y = *(unsigned*)&p1;
        ova.z = *(unsigned*)&p2; ova.w = *(unsigned*)&p3;
        float2 q01 = __half22float2(*(__half2*)&rvb.x);
        float2 q23 = __half22float2(*(__half2*)&rvb.y);
        float2 q45 = __half22float2(*(__half2*)&rvb.z);
        float2 q67 = __half22float2(*(__half2*)&rvb.w);
        __half2 q0 = __floats2half2_rn(fmaxf(c0 * inv + b2.x + q01.x, 0.f), fmaxf(c1 * inv + b2.y + q01.y, 0.f));
        __half2 q1 = __floats2half2_rn(fmaxf(c2 * inv + b2.z + q23.x, 0.f), fmaxf(c3 * inv + b2.w + q23.y, 0.f));
        __half2 q2 = __floats2half2_rn(fmaxf(c4 * inv + b3.x + q45.x, 0.f), fmaxf(c5 * inv + b3.y + q45.y, 0.f));
        __half2 q3 = __floats2half2_rn(fmaxf(c6 * inv + b3.z + q67.x, 0.f), fmaxf(c7 * inv + b3.w + q67.y, 0.f));
        ovb.x = *(unsigned*)&q0; ovb.y = *(unsigned*)&q1;
        ovb.z = *(unsigned*)&q2; ovb.w = *(unsigned*)&q3;
    }
    *(uint4*)&hT[local * LDH + cbase] = ova;
    *(uint4*)&hT[local * LDH + cbase + 8] = ovb;
    __syncthreads();

    int wid = tid >> 5, lane = tid & 31;
    int wm = wid & 3, wn = wid >> 2;
    int m0 = wm * 16, n0 = wn * 16;
    float acc[2][4];
#pragma unroll
    for (int jn = 0; jn < 2; jn++)
#pragma unroll
        for (int q = 0; q < 4; q++) acc[jn][q] = 0.f;
    int lr = lane & 15, lc = lane >> 4;
    uint32_t a_base = smem_u32(&hT[(m0 + lr) * LDH]);
    uint32_t b4 = smem_u32(&Bs[lr * LDB + n0 + (lc << 3)]);
#pragma unroll
    for (int k0 = 0; k0 < 128; k0 += 16) {
        uint32_t a0, a1, a2, a3;
        ldsm_x4(a0, a1, a2, a3, a_base + (k0 + lc * 8) * 2);
        uint32_t bf[2][2];
        ldsm_x4t(bf[0][0], bf[0][1], bf[1][0], bf[1][1], b4 + (k0 * LDB) * 2);
        mma16816(acc[0], a0, a1, a2, a3, bf[0][0], bf[0][1]);
        mma16816(acc[1], a0, a1, a2, a3, bf[1][0], bf[1][1]);
    }
    int quad = lane >> 2, t4 = lane & 3;
#pragma unroll
    for (int jn = 0; jn < 2; jn++) {
        int col = n0 + jn * 8 + t4 * 2;
        int r0 = node0 + m0 + quad, r1 = r0 + 8;
        __half* C; int cc;
        if (col < 32) { C = outl; cc = col; } else { C = outr; cc = col - 32; }
        if (r0 < n) *(__half2*)&C[r0 * 32 + cc] = __floats2half2_rn(acc[jn][0], acc[jn][1]);
        if (r1 < n) *(__half2*)&C[r1 * 32 + cc] = __floats2half2_rn(acc[jn][2], acc[jn][3]);
    }
}

// ---------------- fused post(D=32) + GEMM (32 -> 32|32), PDL prelude on Bs ---------------
__launch_bounds__(256, 6)
__global__ void k_pg32(const int* __restrict__ rowptr, const int* __restrict__ csrc,
                       const __half* __restrict__ hl, const __half* __restrict__ hr,
                       const float* __restrict__ bl, const __half* __restrict__ w,
                       __half* __restrict__ outl, __half* __restrict__ outr, int n) {
    constexpr int LDH = 40;
    constexpr int LDB = 72;
    __shared__ __half hT[64 * LDH];
    __shared__ __half Bs[32 * LDB];
    int tid = threadIdx.x;
    int node0 = blockIdx.x * 64;

    {
        int f = tid * 8;
        int k = f >> 6, j = f & 63;
        *(uint4*)&Bs[k * LDB + j] = *(const uint4*)&w[f];
    }
    GRID_WAIT();

    int local = tid >> 2;
    int sub = tid & 3;
    int node = node0 + local;
    uint4 ov = make_uint4(0u, 0u, 0u, 0u);
    if (node < n) {
        int rs = rowptr[node], re = rowptr[node + 1];
        float a0 = 0.f, a1 = 0.f, a2 = 0.f, a3 = 0.f, a4 = 0.f, a5 = 0.f, a6 = 0.f, a7 = 0.f;
        int t = rs;
        for (; t + 3 < re; t += 4) {
            int s0 = csrc[t], s1 = csrc[t + 1], s2 = csrc[t + 2], s3 = csrc[t + 3];
            uint4 v0 = *(const uint4*)&hl[s0 * 32 + sub * 8];
            uint4 v1 = *(const uint4*)&hl[s1 * 32 + sub * 8];
            uint4 v2 = *(const uint4*)&hl[s2 * 32 + sub * 8];
            uint4 v3 = *(const uint4*)&hl[s3 * 32 + sub * 8];
            ACC8(v0); ACC8(v1); ACC8(v2); ACC8(v3);
        }
        for (; t < re; t++) {
            int s0 = csrc[t];
            uint4 v0 = *(const uint4*)&hl[s0 * 32 + sub * 8];
            ACC8(v0);
        }
        float inv = 1.0f / fmaxf((float)(re - rs), 1.0f);
        uint4 rv = *(const uint4*)&hr[node * 32 + sub * 8];
        float2 r01 = __half22float2(*(__half2*)&rv.x);
        float2 r23 = __half22float2(*(__half2*)&rv.y);
        float2 r45 = __half22float2(*(__half2*)&rv.z);
        float2 r67 = __half22float2(*(__half2*)&rv.w);
        float4 b0 = *(const float4*)&bl[sub * 8];
        float4 b1 = *(const float4*)&bl[sub * 8 + 4];
        __half2 p0 = __floats2half2_rn(fmaxf(a0 * inv + b0.x + r01.x, 0.f), fmaxf(a1 * inv + b0.y + r01.y, 0.f));
        __half2 p1 = __floats2half2_rn(fmaxf(a2 * inv + b0.z + r23.x, 0.f), fmaxf(a3 * inv + b0.w + r23.y, 0.f));
        __half2 p2 = __floats2half2_rn(fmaxf(a4 * inv + b1.x + r45.x, 0.f), fmaxf(a5 * inv + b1.y + r45.y, 0.f));
        __half2 p3 = __floats2half2_rn(fmaxf(a6 * inv + b1.z + r67.x, 0.f), fmaxf(a7 * inv + b1.w + r67.y, 0.f));
        ov.x = *(unsigned*)&p0; ov.y = *(unsigned*)&p1;
        ov.z = *(unsigned*)&p2; ov.w = *(unsigned*)&p3;
    }
    *(uint4*)&hT[local * LDH + sub * 8] = ov;
    __syncthreads();

    int wid = tid >> 5, lane = tid & 31;
    int wm = wid & 3, wn = wid >> 2;
    int m0 = wm * 16, n0 = wn * 32;
    float acc[4][4];
#pragma unroll
    for (int jn = 0; jn < 4; jn++)
#pragma unroll
        for (int q = 0; q < 4; q++) acc[jn][q] = 0.f;
    int lr = lane & 15, lc = lane >> 4;
    uint32_t a_base = smem_u32(&hT[(m0 + lr) * LDH]);
    uint32_t b4 = smem_u32(&Bs[lr * LDB + n0 + (lc << 3)]);
#pragma unroll
    for (int k0 = 0; k0 < 32; k0 += 16) {
        uint32_t a0, a1, a2, a3;
        ldsm_x4(a0, a1, a2, a3, a_base + (k0 + lc * 8) * 2);
        uint32_t bf[4][2];
        ldsm_x4t(bf[0][0], bf[0][1], bf[1][0], bf[1][1], b4 + (k0 * LDB) * 2);
        ldsm_x4t(bf[2][0], bf[2][1], bf[3][0], bf[3][1], b4 + (k0 * LDB + 16) * 2);
#pragma unroll
        for (int jn = 0; jn < 4; jn++)
            mma16816(acc[jn], a0, a1, a2, a3, bf[jn][0], bf[jn][1]);
    }
    int quad = lane >> 2, t4 = lane & 3;
#pragma unroll
    for (int jn = 0; jn < 4; jn++) {
        int col = n0 + jn * 8 + t4 * 2;
        int r0 = node0 + m0 + quad, r1 = r0 + 8;
        __half* C; int cc;
        if (col < 32) { C = outl; cc = col; } else { C = outr; cc = col - 32; }
        if (r0 < n) *(__half2*)&C[r0 * 32 + cc] = __floats2half2_rn(acc[jn][0], acc[jn][1]);
        if (r1 < n) *(__half2*)&C[r1 * 32 + cc] = __floats2half2_rn(acc[jn][2], acc[jn][3]);
    }
}

// ---------------- layer 5 post fused with output head ----------------
__launch_bounds__(256, 8)
__global__ void k_post_out(const int* __restrict__ rowptr, const int* __restrict__ csrc,
                           const __half* __restrict__ hl, const __half* __restrict__ hr,
                           const float* __restrict__ bl,
                           const float* __restrict__ Wo, const float* __restrict__ bo,
                           float* __restrict__ out, int n) {
    constexpr int D = 32;
    constexpr int LPN = 4;
    int tid = blockIdx.x * blockDim.x + threadIdx.x;
    int node = tid / LPN;
    int sub = tid % LPN;
    GRID_WAIT();
    if (node >= n) return;
    int rs = rowptr[node], re = rowptr[node + 1];
    float a0 = 0.f, a1 = 0.f, a2 = 0.f, a3 = 0.f, a4 = 0.f, a5 = 0.f, a6 = 0.f, a7 = 0.f;
    int t = rs;
    for (; t + 3 < re; t += 4) {
        int s0 = csrc[t], s1 = csrc[t + 1], s2 = csrc[t + 2], s3 = csrc[t + 3];
        uint4 v0 = *(const uint4*)&hl[s0 * D + sub * 8];
        uint4 v1 = *(const uint4*)&hl[s1 * D + sub * 8];
        uint4 v2 = *(const uint4*)&hl[s2 * D + sub * 8];
        uint4 v3 = *(const uint4*)&hl[s3 * D + sub * 8];
        ACC8(v0); ACC8(v1); ACC8(v2); ACC8(v3);
    }
    for (; t < re; t++) {
        int s0 = csrc[t];
        uint4 v0 = *(const uint4*)&hl[s0 * D + sub * 8];
        ACC8(v0);
    }
    float dv = (float)(re - rs);
    float inv = 1.0f / fmaxf(dv, 1.0f);
    uint4 rv = *(const uint4*)&hr[node * D + sub * 8];
    float2 r01 = __half22float2(*(__half2*)&rv.x);
    float2 r23 = __half22float2(*(__half2*)&rv.y);
    float2 r45 = __half22float2(*(__half2*)&rv.z);
    float2 r67 = __half22float2(*(__half2*)&rv.w);
    float4 b0 = *(const float4*)&bl[sub * 8];
    float4 b1 = *(const float4*)&bl[sub * 8 + 4];
    float4 w0 = *(const float4*)&Wo[sub * 8];
    float4 w1 = *(const float4*)&Wo[sub * 8 + 4];
    float s = 0.f;
    s += fmaxf(a0 * inv + b0.x + r01.x, 0.f) * w0.x;
    s += fmaxf(a1 * inv + b0.y + r01.y, 0.f) * w0.y;
    s += fmaxf(a2 * inv + b0.z + r23.x, 0.f) * w0.z;
    s += fmaxf(a3 * inv + b0.w + r23.y, 0.f) * w0.w;
    s += fmaxf(a4 * inv + b1.x + r45.x, 0.f) * w1.x;
    s += fmaxf(a5 * inv + b1.y + r45.y, 0.f) * w1.y;
    s += fmaxf(a6 * inv + b1.z + r67.x, 0.f) * w1.z;
    s += fmaxf(a7 * inv + b1.w + r67.y, 0.f) * w1.w;
    s += __shfl_xor_sync(0xffffffffu, s, 1);
    s += __shfl_xor_sync(0xffffffffu, s, 2);
    if (sub == 0) out[node] = s + bo[0];
}

// ---------------- PDL launch helper ----------------
template <typename F, typename... Args>
static void launch_pdl(F f, dim3 grid, dim3 block, size_t smem, Args... args) {
    cudaLaunchConfig_t cfg = {};
    cfg.gridDim = grid;
    cfg.blockDim = block;
    cfg.dynamicSmemBytes = smem;
    cfg.stream = 0;
    cudaLaunchAttribute attr[1];
    attr[0].id = cudaLaunchAttributeProgrammaticStreamSerialization;
    attr[0].val.programmaticStreamSerializationAllowed = 1;
    cfg.attrs = attr;
    cfg.numAttrs = 1;
    cudaLaunchKernelEx(&cfg, f, args...);
}

// ---------------- launch ----------------
extern "C" void kernel_launch(void* const* d_in, const int* in_sizes, int n_in,
                              void* d_out, int out_size) {
    const float* x   = (const float*)d_in[0];
    const int*   ei  = (const int*)d_in[1];
    const float* Wl1 = (const float*)d_in[3];
    const float* bl1 = (const float*)d_in[4];
    const float* Wr1 = (const float*)d_in[5];
    const float* Wl2 = (const float*)d_in[6];
    const float* bl2 = (const float*)d_in[7];
    const float* Wr2 = (const float*)d_in[8];
    const float* Wl3 = (const float*)d_in[9];
    const float* bl3 = (const float*)d_in[10];
    const float* Wr3 = (const float*)d_in[11];
    const float* Wl4 = (const float*)d_in[12];
    const float* bl4 = (const float*)d_in[13];
    const float* Wr4 = (const float*)d_in[14];
    const float* Wl5 = (const float*)d_in[15];
    const float* bl5 = (const float*)d_in[16];
    const float* Wr5 = (const float*)d_in[17];
    const float* Wo  = (const float*)d_in[18];
    const float* bo  = (const float*)d_in[19];
    float* out = (float*)d_out;

    int n = in_sizes[0] / 2;
    int E = in_sizes[1] / 2;

    __half *p_h, *p_hl, *p_hr, *p_w2, *p_w3, *p_w4, *p_w5;
    float* p_aggx;
    int *p_cnt, *p_rowptr, *p_cursor, *p_csrc;
    unsigned* p_state;
    cudaGetSymbolAddress((void**)&p_h, g_h);
    cudaGetSymbolAddress((void**)&p_hl, g_hl);
    cudaGetSymbolAddress((void**)&p_hr, g_hr);
    cudaGetSymbolAddress((void**)&p_aggx, g_aggx);
    cudaGetSymbolAddress((void**)&p_w2, g_w2);
    cudaGetSymbolAddress((void**)&p_w3, g_w3);
    cudaGetSymbolAddress((void**)&p_w4, g_w4);
    cudaGetSymbolAddress((void**)&p_w5, g_w5);
    cudaGetSymbolAddress((void**)&p_cnt, g_cnt);
    cudaGetSymbolAddress((void**)&p_rowptr, g_rowptr);
    cudaGetSymbolAddress((void**)&p_cursor, g_cursor);
    cudaGetSymbolAddress((void**)&p_csrc, g_csrc);
    cudaGetSymbolAddress((void**)&p_state, g_state);

    cudaFuncSetAttribute(k_gemm2, cudaFuncAttributeMaxDynamicSharedMemorySize, 69632);

    int NB = (n + 1023) / 1024;
    int eq = ((E + 3) / 4 + 255) / 256;
    int gb = (n + 127) / 128;
    int g_l1 = (n + 63) / 64;
    int g_64 = (n + 63) / 64;
    int g_4  = (n * 4 + 255) / 256;

    __half* hA = p_h;
    __half* hB = p_h + NN * 32;

    // CSR build (first launch plain; rest PDL-marked)
    k_count<<<eq, 256>>>(ei, p_cnt, E, Wl2, Wr2, Wl3, Wr3, Wl4, Wr4, Wl5, Wr5,
                         p_w2, p_w3, p_w4, p_w5, p_state, p_aggx, n);
    launch_pdl(k_scan_lb, dim3(NB), dim3(256), 0, p_cnt, (volatile unsigned*)p_state, p_rowptr, p_cursor, n);
    launch_pdl(k_fill, dim3(eq), dim3(256), 0, ei, x, p_cursor, p_csrc, (float2*)p_aggx, E);

    // layer 1 (2 -> 128)
    launch_pdl(k_layer1r, dim3(g_l1), dim3(256), 0, x, p_aggx, p_rowptr, Wl1, bl1, Wr1, p_h, n);

    // layer 2 (128 -> 128)
    launch_pdl(k_gemm2, dim3(gb, 2), dim3(512), (size_t)69632,
               (const __half*)p_h, (const __half*)p_w2, p_hl, p_hr, n);

    // post(layer2) + GEMM3 fused -> hl3 in hA, hr3 in hB
    launch_pdl(k_pg128, dim3(g_64), dim3(512), 0,
               (const int*)p_rowptr, (const int*)p_csrc, (const __half*)p_hl, (const __half*)p_hr,
               bl2, (const __half*)p_w3, hA, hB, n);

    // post(layer3) + GEMM4 -> p_hl, p_hr
    launch_pdl(k_pg32, dim3(g_64), dim3(256), 0,
               (const int*)p_rowptr, (const int*)p_csrc, (const __half*)hA, (const __half*)hB,
               bl3, (const __half*)p_w4, p_hl, p_hr, n);

    // post(layer4) + GEMM5 -> hA, hB
    launch_pdl(k_pg32, dim3(g_64), dim3(256), 0,
               (const int*)p_rowptr, (const int*)p_csrc, (const __half*)p_hl, (const __half*)p_hr,
               bl4, (const __half*)p_w5, hA, hB, n);

    // post(layer5) + output head
    launch_pdl(k_post_out, dim3(g_4), dim3(256), 0,
               (const int*)p_rowptr, (const int*)p_csrc, (const __half*)hA, (const __half*)hB,
               bl5, Wo, bo, out, n);
}